// round 10
// baseline (speedup 1.0000x reference)
#include <cuda_runtime.h>
#include <cuda_bf16.h>
#include <cstdint>

// Shapes (fixed by problem)
#define Bv 4
#define Sv 512
#define Hv 256

// Scratch (device globals: no allocation allowed in kernel_launch)
__device__ float g_P[(Bv * Sv) * (2 * Hv)];   // [m][0:256]=h@W_t, [256:512]=h@W_t' + b_h
__device__ float g_S[Bv * Sv * Sv];           // sigmoid(scores)
__device__ float g_AW[Bv * Sv * Sv];          // softmax(attention weights)

__device__ __forceinline__ float fast_tanh(float x) {
    float y;
    asm("tanh.approx.f32 %0, %1;" : "=f"(y) : "f"(x));
    return y;
}

// ---------------------------------------------------------------------------
// Kernel 1: fused projection GEMM
//   g_P[M=2048][N=512] = h[2048][256] @ [W_t | W_t'] ; cols >=256 get +b_h
// TILE 32(m) x 64(n), BK=32, 256 threads, 2x4 microtile, float4 gmem I/O,
// A transposed in smem (k-major) -> inner loop: LDS.64 + LDS.128 + 8 FFMA.
// Grid 8 x 64 = 512 blocks.
// ---------------------------------------------------------------------------
__global__ __launch_bounds__(256) void k1_proj(
    const float* __restrict__ h,
    const float* __restrict__ Wt,
    const float* __restrict__ Wtp,
    const float* __restrict__ bh)
{
    __shared__ alignas(16) float sA[32][34];   // [k][m]
    __shared__ alignas(16) float sB[32][68];   // [k][n]

    const int tid = threadIdx.x;
    const int bm  = blockIdx.y * 32;
    const int bn  = blockIdx.x * 64;
    const int tx  = tid & 15;        // n: 16 * 4
    const int ty  = tid >> 4;        // m: 16 * 2

    const bool second = (bn >= Hv);
    const float* __restrict__ W = second ? Wtp : Wt;
    const int wcol = bn & (Hv - 1);

    // A-load mapping: one float4 per thread per k-step
    const int ar  = tid >> 3;         // 0..31 (m row)
    const int ac4 = (tid & 7) * 4;    // 0..28 (k col)

    float acc[2][4] = {};

    for (int k0 = 0; k0 < Hv; k0 += 32) {
        float4 av = *(const float4*)&h[(bm + ar) * Hv + k0 + ac4];
        sA[ac4 + 0][ar] = av.x;
        sA[ac4 + 1][ar] = av.y;
        sA[ac4 + 2][ar] = av.z;
        sA[ac4 + 3][ar] = av.w;
        #pragma unroll
        for (int j = 0; j < 2; j++) {
            int idx = tid + j * 256;
            int rb  = idx >> 4;            // 0..31 (k)
            int cb4 = (idx & 15) * 4;      // 0..60 (n)
            *(float4*)&sB[rb][cb4] =
                *(const float4*)&W[(k0 + rb) * Hv + wcol + cb4];
        }
        __syncthreads();

        #pragma unroll
        for (int k = 0; k < 32; k++) {
            float2 a = *(const float2*)&sA[k][ty * 2];
            float4 b = *(const float4*)&sB[k][tx * 4];
            acc[0][0] = fmaf(a.x, b.x, acc[0][0]);
            acc[0][1] = fmaf(a.x, b.y, acc[0][1]);
            acc[0][2] = fmaf(a.x, b.z, acc[0][2]);
            acc[0][3] = fmaf(a.x, b.w, acc[0][3]);
            acc[1][0] = fmaf(a.y, b.x, acc[1][0]);
            acc[1][1] = fmaf(a.y, b.y, acc[1][1]);
            acc[1][2] = fmaf(a.y, b.z, acc[1][2]);
            acc[1][3] = fmaf(a.y, b.w, acc[1][3]);
        }
        __syncthreads();
    }

    float4 bias = make_float4(0.f, 0.f, 0.f, 0.f);
    if (second) bias = *(const float4*)&bh[wcol + tx * 4];

    #pragma unroll
    for (int i = 0; i < 2; i++) {
        int m = bm + ty * 2 + i;
        float4 v = make_float4(acc[i][0] + bias.x, acc[i][1] + bias.y,
                               acc[i][2] + bias.z, acc[i][3] + bias.w);
        *(float4*)&g_P[m * (2 * Hv) + bn + tx * 4] = v;
    }
}

// ---------------------------------------------------------------------------
// Kernel 2: pairwise scores (MUFU-bound, near the tanh floor)
//   S[b,t,t'] = sigmoid( b_a + sum_h W_a[h] * tanh(ht[b,t,h] + htp[b,t',h]) )
// ---------------------------------------------------------------------------
#define TT 32
#define HC 64
__global__ __launch_bounds__(256) void k2_scores(
    const float* __restrict__ Wa,
    const float* __restrict__ ba)
{
    __shared__ float sA[TT][HC + 1];
    __shared__ float sB[TT][HC + 1];
    __shared__ float sW[HC];

    const int b   = blockIdx.z;
    const int t0  = blockIdx.y * TT;
    const int tp0 = blockIdx.x * TT;
    const int tid = threadIdx.x;
    const int tx = tid & 15, ty = tid >> 4;

    const float* Pb = g_P + (size_t)b * Sv * (2 * Hv);

    float acc00 = 0.f, acc01 = 0.f, acc10 = 0.f, acc11 = 0.f;

    for (int h0 = 0; h0 < Hv; h0 += HC) {
        #pragma unroll
        for (int i = 0; i < 8; i++) {
            int idx = tid + i * 256;
            int r = idx >> 6, c = idx & 63;
            sA[r][c] = Pb[(t0  + r) * (2 * Hv) + h0 + c];          // ht rows
            sB[r][c] = Pb[(tp0 + r) * (2 * Hv) + Hv + h0 + c];     // htp+b_h rows
        }
        if (tid < HC) sW[tid] = Wa[h0 + tid];
        __syncthreads();

        #pragma unroll
        for (int hh = 0; hh < HC; hh++) {
            float w  = sW[hh];
            float a0 = sA[2 * ty][hh];
            float a1 = sA[2 * ty + 1][hh];
            float b0 = sB[2 * tx][hh];
            float b1 = sB[2 * tx + 1][hh];
            acc00 = fmaf(w, fast_tanh(a0 + b0), acc00);
            acc01 = fmaf(w, fast_tanh(a0 + b1), acc01);
            acc10 = fmaf(w, fast_tanh(a1 + b0), acc10);
            acc11 = fmaf(w, fast_tanh(a1 + b1), acc11);
        }
        __syncthreads();
    }

    const float bav = ba[0];
    float* Sb = g_S + (size_t)b * Sv * Sv;
    float r[2][2] = {{acc00, acc01}, {acc10, acc11}};
    #pragma unroll
    for (int i = 0; i < 2; i++) {
        #pragma unroll
        for (int j = 0; j < 2; j++) {
            float x = r[i][j] + bav;
            float sg = 1.0f / (1.0f + __expf(-x));
            Sb[(t0 + 2 * ty + i) * Sv + (tp0 + 2 * tx + j)] = sg;
        }
    }
}

// ---------------------------------------------------------------------------
// Kernel 3: row softmax. One warp per row of 512 (float4 vectorized).
// ---------------------------------------------------------------------------
__global__ __launch_bounds__(256) void k3_softmax(float* __restrict__ aw_out)
{
    const int row  = blockIdx.x * 8 + (threadIdx.x >> 5);
    const int lane = threadIdx.x & 31;
    const float4* src = (const float4*)(g_S + (size_t)row * Sv);

    float4 v[4];
    float mx = -1e30f;
    #pragma unroll
    for (int i = 0; i < 4; i++) {
        v[i] = src[i * 32 + lane];
        mx = fmaxf(mx, fmaxf(fmaxf(v[i].x, v[i].y), fmaxf(v[i].z, v[i].w)));
    }
    #pragma unroll
    for (int o = 16; o > 0; o >>= 1)
        mx = fmaxf(mx, __shfl_xor_sync(0xffffffffu, mx, o));

    float sum = 0.f;
    #pragma unroll
    for (int i = 0; i < 4; i++) {
        v[i].x = __expf(v[i].x - mx);
        v[i].y = __expf(v[i].y - mx);
        v[i].z = __expf(v[i].z - mx);
        v[i].w = __expf(v[i].w - mx);
        sum += v[i].x + v[i].y + v[i].z + v[i].w;
    }
    #pragma unroll
    for (int o = 16; o > 0; o >>= 1)
        sum += __shfl_xor_sync(0xffffffffu, sum, o);

    const float inv = 1.0f / sum;
    float4* dst = (float4*)(g_AW + (size_t)row * Sv);
    #pragma unroll
    for (int i = 0; i < 4; i++) {
        float4 o4 = v[i];
        o4.x *= inv; o4.y *= inv; o4.z *= inv; o4.w *= inv;
        dst[i * 32 + lane] = o4;
    }
    if (aw_out) {
        float4* dst2 = (float4*)(aw_out + (size_t)row * Sv);
        #pragma unroll
        for (int i = 0; i < 4; i++) {
            float4 o4 = v[i];
            o4.x *= inv; o4.y *= inv; o4.z *= inv; o4.w *= inv;
            dst2[i * 32 + lane] = o4;
        }
    }
}

// ---------------------------------------------------------------------------
// Kernel 4: output[b] = AW[b](512x512) @ h[b](512x256)
// Same tiling as k1: 32x64 tile, BK=32, 256 threads, 2x4 microtile.
// Grid (256/64=4, 512/32=16, 4) = 256 blocks.
// ---------------------------------------------------------------------------
__global__ __launch_bounds__(256) void k4_out(
    const float* __restrict__ h,
    float* __restrict__ out)
{
    __shared__ alignas(16) float sA[32][34];   // [k][m]
    __shared__ alignas(16) float sB[32][68];   // [k][n]

    const int b   = blockIdx.z;
    const int bm  = blockIdx.y * 32;   // t rows
    const int bn  = blockIdx.x * 64;   // h cols
    const int tid = threadIdx.x;
    const int tx  = tid & 15;
    const int ty  = tid >> 4;

    const float* __restrict__ A  = g_AW + (size_t)b * Sv * Sv;   // 512x512
    const float* __restrict__ Bm = h + (size_t)b * Sv * Hv;      // 512x256
    float* C = out + (size_t)b * Sv * Hv;

    const int ar  = tid >> 3;
    const int ac4 = (tid & 7) * 4;

    float acc[2][4] = {};

    for (int k0 = 0; k0 < Sv; k0 += 32) {
        float4 av = *(const float4*)&A[(bm + ar) * Sv + k0 + ac4];
        sA[ac4 + 0][ar] = av.x;
        sA[ac4 + 1][ar] = av.y;
        sA[ac4 + 2][ar] = av.z;
        sA[ac4 + 3][ar] = av.w;
        #pragma unroll
        for (int j = 0; j < 2; j++) {
            int idx = tid + j * 256;
            int rb  = idx >> 4;
            int cb4 = (idx & 15) * 4;
            *(float4*)&sB[rb][cb4] =
                *(const float4*)&Bm[(k0 + rb) * Hv + bn + cb4];
        }
        __syncthreads();

        #pragma unroll
        for (int k = 0; k < 32; k++) {
            float2 a = *(const float2*)&sA[k][ty * 2];
            float4 bb = *(const float4*)&sB[k][tx * 4];
            acc[0][0] = fmaf(a.x, bb.x, acc[0][0]);
            acc[0][1] = fmaf(a.x, bb.y, acc[0][1]);
            acc[0][2] = fmaf(a.x, bb.z, acc[0][2]);
            acc[0][3] = fmaf(a.x, bb.w, acc[0][3]);
            acc[1][0] = fmaf(a.y, bb.x, acc[1][0]);
            acc[1][1] = fmaf(a.y, bb.y, acc[1][1]);
            acc[1][2] = fmaf(a.y, bb.z, acc[1][2]);
            acc[1][3] = fmaf(a.y, bb.w, acc[1][3]);
        }
        __syncthreads();
    }

    #pragma unroll
    for (int i = 0; i < 2; i++) {
        int m = bm + ty * 2 + i;
        float4 v = make_float4(acc[i][0], acc[i][1], acc[i][2], acc[i][3]);
        *(float4*)&C[m * Hv + bn + tx * 4] = v;
    }
}

// ---------------------------------------------------------------------------
extern "C" void kernel_launch(void* const* d_in, const int* in_sizes, int n_in,
                              void* d_out, int out_size)
{
    const float* h   = (const float*)d_in[0];  // (4,512,256)
    const float* Wt  = (const float*)d_in[1];  // (256,256)
    const float* Wtp = (const float*)d_in[2];  // (256,256)
    const float* bh  = (const float*)d_in[3];  // (256,)
    const float* Wa  = (const float*)d_in[4];  // (256,)
    const float* ba  = (const float*)d_in[5];  // ()

    float* out = (float*)d_out;
    const int out_elems = Bv * Sv * Hv;        // 524288
    const int aw_elems  = Bv * Sv * Sv;        // 1048576
    float* aw_out = (out_size >= out_elems + aw_elems) ? out + out_elems : nullptr;

    // k1: projections  g_P[2048][512]
    {
        dim3 grid((2 * Hv) / 64, (Bv * Sv) / 32);   // 8 x 64 = 512 blocks
        k1_proj<<<grid, 256>>>(h, Wt, Wtp, bh);
    }
    // k2: pairwise tanh scores + sigmoid
    {
        dim3 grid(Sv / TT, Sv / TT, Bv);            // 16 x 16 x 4
        k2_scores<<<grid, 256>>>(Wa, ba);
    }
    // k3: softmax rows
    {
        k3_softmax<<<(Bv * Sv) / 8, 256>>>(aw_out);
    }
    // k4: output = AW @ h
    {
        dim3 grid(Hv / 64, Sv / 32, Bv);            // 4 x 16 x 4 = 256 blocks
        k4_out<<<grid, 256>>>(h, out);
    }
}

// round 13
// speedup vs baseline: 1.0042x; 1.0042x over previous
#include <cuda_runtime.h>
#include <cuda_bf16.h>
#include <cstdint>

// Shapes (fixed by problem)
#define Bv 4
#define Sv 512
#define Hv 256

// Scratch (device globals: no allocation allowed in kernel_launch)
__device__ float g_P[(Bv * Sv) * (2 * Hv)];   // [m][0:256]=h@W_t, [256:512]=h@W_t' + b_h
__device__ float g_S[Bv * Sv * Sv];           // sigmoid(scores)
__device__ float g_AW[Bv * Sv * Sv];          // softmax(attention weights)

__device__ __forceinline__ float fast_tanh(float x) {
    float y;
    asm("tanh.approx.f32 %0, %1;" : "=f"(y) : "f"(x));
    return y;
}

// ---------------------------------------------------------------------------
// Kernel 1: fused projection GEMM
//   g_P[M=2048][N=512] = h[2048][256] @ [W_t | W_t'] ; cols >=256 get +b_h
// TILE 32(m) x 64(n), BK=32, 256 threads, 2x4 microtile, float4 gmem I/O,
// A transposed in smem (k-major) -> inner loop: LDS.64 + LDS.128 + 8 FFMA.
// Grid 8 x 64 = 512 blocks.
// ---------------------------------------------------------------------------
__global__ __launch_bounds__(256) void k1_proj(
    const float* __restrict__ h,
    const float* __restrict__ Wt,
    const float* __restrict__ Wtp,
    const float* __restrict__ bh)
{
    __shared__ alignas(16) float sA[32][34];   // [k][m]
    __shared__ alignas(16) float sB[32][68];   // [k][n]

    const int tid = threadIdx.x;
    const int bm  = blockIdx.y * 32;
    const int bn  = blockIdx.x * 64;
    const int tx  = tid & 15;        // n: 16 * 4
    const int ty  = tid >> 4;        // m: 16 * 2

    const bool second = (bn >= Hv);
    const float* __restrict__ W = second ? Wtp : Wt;
    const int wcol = bn & (Hv - 1);

    // A-load mapping: one float4 per thread per k-step
    const int ar  = tid >> 3;         // 0..31 (m row)
    const int ac4 = (tid & 7) * 4;    // 0..28 (k col)

    float acc[2][4] = {};

    for (int k0 = 0; k0 < Hv; k0 += 32) {
        float4 av = *(const float4*)&h[(bm + ar) * Hv + k0 + ac4];
        sA[ac4 + 0][ar] = av.x;
        sA[ac4 + 1][ar] = av.y;
        sA[ac4 + 2][ar] = av.z;
        sA[ac4 + 3][ar] = av.w;
        #pragma unroll
        for (int j = 0; j < 2; j++) {
            int idx = tid + j * 256;
            int rb  = idx >> 4;            // 0..31 (k)
            int cb4 = (idx & 15) * 4;      // 0..60 (n)
            *(float4*)&sB[rb][cb4] =
                *(const float4*)&W[(k0 + rb) * Hv + wcol + cb4];
        }
        __syncthreads();

        #pragma unroll
        for (int k = 0; k < 32; k++) {
            float2 a = *(const float2*)&sA[k][ty * 2];
            float4 b = *(const float4*)&sB[k][tx * 4];
            acc[0][0] = fmaf(a.x, b.x, acc[0][0]);
            acc[0][1] = fmaf(a.x, b.y, acc[0][1]);
            acc[0][2] = fmaf(a.x, b.z, acc[0][2]);
            acc[0][3] = fmaf(a.x, b.w, acc[0][3]);
            acc[1][0] = fmaf(a.y, b.x, acc[1][0]);
            acc[1][1] = fmaf(a.y, b.y, acc[1][1]);
            acc[1][2] = fmaf(a.y, b.z, acc[1][2]);
            acc[1][3] = fmaf(a.y, b.w, acc[1][3]);
        }
        __syncthreads();
    }

    float4 bias = make_float4(0.f, 0.f, 0.f, 0.f);
    if (second) bias = *(const float4*)&bh[wcol + tx * 4];

    #pragma unroll
    for (int i = 0; i < 2; i++) {
        int m = bm + ty * 2 + i;
        float4 v = make_float4(acc[i][0] + bias.x, acc[i][1] + bias.y,
                               acc[i][2] + bias.z, acc[i][3] + bias.w);
        *(float4*)&g_P[m * (2 * Hv) + bn + tx * 4] = v;
    }
}

// ---------------------------------------------------------------------------
// Kernel 2: pairwise scores (MUFU-bound, near the tanh floor)
//   S[b,t,t'] = sigmoid( b_a + sum_h W_a[h] * tanh(ht[b,t,h] + htp[b,t',h]) )
// ---------------------------------------------------------------------------
#define TT 32
#define HC 64
__global__ __launch_bounds__(256) void k2_scores(
    const float* __restrict__ Wa,
    const float* __restrict__ ba)
{
    __shared__ float sA[TT][HC + 1];
    __shared__ float sB[TT][HC + 1];
    __shared__ float sW[HC];

    const int b   = blockIdx.z;
    const int t0  = blockIdx.y * TT;
    const int tp0 = blockIdx.x * TT;
    const int tid = threadIdx.x;
    const int tx = tid & 15, ty = tid >> 4;

    const float* Pb = g_P + (size_t)b * Sv * (2 * Hv);

    float acc00 = 0.f, acc01 = 0.f, acc10 = 0.f, acc11 = 0.f;

    for (int h0 = 0; h0 < Hv; h0 += HC) {
        #pragma unroll
        for (int i = 0; i < 8; i++) {
            int idx = tid + i * 256;
            int r = idx >> 6, c = idx & 63;
            sA[r][c] = Pb[(t0  + r) * (2 * Hv) + h0 + c];          // ht rows
            sB[r][c] = Pb[(tp0 + r) * (2 * Hv) + Hv + h0 + c];     // htp+b_h rows
        }
        if (tid < HC) sW[tid] = Wa[h0 + tid];
        __syncthreads();

        #pragma unroll
        for (int hh = 0; hh < HC; hh++) {
            float w  = sW[hh];
            float a0 = sA[2 * ty][hh];
            float a1 = sA[2 * ty + 1][hh];
            float b0 = sB[2 * tx][hh];
            float b1 = sB[2 * tx + 1][hh];
            acc00 = fmaf(w, fast_tanh(a0 + b0), acc00);
            acc01 = fmaf(w, fast_tanh(a0 + b1), acc01);
            acc10 = fmaf(w, fast_tanh(a1 + b0), acc10);
            acc11 = fmaf(w, fast_tanh(a1 + b1), acc11);
        }
        __syncthreads();
    }

    const float bav = ba[0];
    float* Sb = g_S + (size_t)b * Sv * Sv;
    float r[2][2] = {{acc00, acc01}, {acc10, acc11}};
    #pragma unroll
    for (int i = 0; i < 2; i++) {
        #pragma unroll
        for (int j = 0; j < 2; j++) {
            float x = r[i][j] + bav;
            float sg = 1.0f / (1.0f + __expf(-x));
            Sb[(t0 + 2 * ty + i) * Sv + (tp0 + 2 * tx + j)] = sg;
        }
    }
}

// ---------------------------------------------------------------------------
// Kernel 3: row softmax. One warp per row of 512 (float4 vectorized).
// ---------------------------------------------------------------------------
__global__ __launch_bounds__(256) void k3_softmax(float* __restrict__ aw_out)
{
    const int row  = blockIdx.x * 8 + (threadIdx.x >> 5);
    const int lane = threadIdx.x & 31;
    const float4* src = (const float4*)(g_S + (size_t)row * Sv);

    float4 v[4];
    float mx = -1e30f;
    #pragma unroll
    for (int i = 0; i < 4; i++) {
        v[i] = src[i * 32 + lane];
        mx = fmaxf(mx, fmaxf(fmaxf(v[i].x, v[i].y), fmaxf(v[i].z, v[i].w)));
    }
    #pragma unroll
    for (int o = 16; o > 0; o >>= 1)
        mx = fmaxf(mx, __shfl_xor_sync(0xffffffffu, mx, o));

    float sum = 0.f;
    #pragma unroll
    for (int i = 0; i < 4; i++) {
        v[i].x = __expf(v[i].x - mx);
        v[i].y = __expf(v[i].y - mx);
        v[i].z = __expf(v[i].z - mx);
        v[i].w = __expf(v[i].w - mx);
        sum += v[i].x + v[i].y + v[i].z + v[i].w;
    }
    #pragma unroll
    for (int o = 16; o > 0; o >>= 1)
        sum += __shfl_xor_sync(0xffffffffu, sum, o);

    const float inv = 1.0f / sum;
    float4* dst = (float4*)(g_AW + (size_t)row * Sv);
    #pragma unroll
    for (int i = 0; i < 4; i++) {
        float4 o4 = v[i];
        o4.x *= inv; o4.y *= inv; o4.z *= inv; o4.w *= inv;
        dst[i * 32 + lane] = o4;
    }
    if (aw_out) {
        float4* dst2 = (float4*)(aw_out + (size_t)row * Sv);
        #pragma unroll
        for (int i = 0; i < 4; i++) {
            float4 o4 = v[i];
            o4.x *= inv; o4.y *= inv; o4.z *= inv; o4.w *= inv;
            dst2[i * 32 + lane] = o4;
        }
    }
}

// ---------------------------------------------------------------------------
// Kernel 4: output[b] = AW[b](512x512) @ h[b](512x256)
// Same tiling as k1: 32x64 tile, BK=32, 256 threads, 2x4 microtile.
// Grid (256/64=4, 512/32=16, 4) = 256 blocks.
// ---------------------------------------------------------------------------
__global__ __launch_bounds__(256) void k4_out(
    const float* __restrict__ h,
    float* __restrict__ out)
{
    __shared__ alignas(16) float sA[32][34];   // [k][m]
    __shared__ alignas(16) float sB[32][68];   // [k][n]

    const int b   = blockIdx.z;
    const int bm  = blockIdx.y * 32;   // t rows
    const int bn  = blockIdx.x * 64;   // h cols
    const int tid = threadIdx.x;
    const int tx  = tid & 15;
    const int ty  = tid >> 4;

    const float* __restrict__ A  = g_AW + (size_t)b * Sv * Sv;   // 512x512
    const float* __restrict__ Bm = h + (size_t)b * Sv * Hv;      // 512x256
    float* C = out + (size_t)b * Sv * Hv;

    const int ar  = tid >> 3;
    const int ac4 = (tid & 7) * 4;

    float acc[2][4] = {};

    for (int k0 = 0; k0 < Sv; k0 += 32) {
        float4 av = *(const float4*)&A[(bm + ar) * Sv + k0 + ac4];
        sA[ac4 + 0][ar] = av.x;
        sA[ac4 + 1][ar] = av.y;
        sA[ac4 + 2][ar] = av.z;
        sA[ac4 + 3][ar] = av.w;
        #pragma unroll
        for (int j = 0; j < 2; j++) {
            int idx = tid + j * 256;
            int rb  = idx >> 4;
            int cb4 = (idx & 15) * 4;
            *(float4*)&sB[rb][cb4] =
                *(const float4*)&Bm[(k0 + rb) * Hv + bn + cb4];
        }
        __syncthreads();

        #pragma unroll
        for (int k = 0; k < 32; k++) {
            float2 a = *(const float2*)&sA[k][ty * 2];
            float4 bb = *(const float4*)&sB[k][tx * 4];
            acc[0][0] = fmaf(a.x, bb.x, acc[0][0]);
            acc[0][1] = fmaf(a.x, bb.y, acc[0][1]);
            acc[0][2] = fmaf(a.x, bb.z, acc[0][2]);
            acc[0][3] = fmaf(a.x, bb.w, acc[0][3]);
            acc[1][0] = fmaf(a.y, bb.x, acc[1][0]);
            acc[1][1] = fmaf(a.y, bb.y, acc[1][1]);
            acc[1][2] = fmaf(a.y, bb.z, acc[1][2]);
            acc[1][3] = fmaf(a.y, bb.w, acc[1][3]);
        }
        __syncthreads();
    }

    #pragma unroll
    for (int i = 0; i < 2; i++) {
        int m = bm + ty * 2 + i;
        float4 v = make_float4(acc[i][0], acc[i][1], acc[i][2], acc[i][3]);
        *(float4*)&C[m * Hv + bn + tx * 4] = v;
    }
}

// ---------------------------------------------------------------------------
extern "C" void kernel_launch(void* const* d_in, const int* in_sizes, int n_in,
                              void* d_out, int out_size)
{
    const float* h   = (const float*)d_in[0];  // (4,512,256)
    const float* Wt  = (const float*)d_in[1];  // (256,256)
    const float* Wtp = (const float*)d_in[2];  // (256,256)
    const float* bh  = (const float*)d_in[3];  // (256,)
    const float* Wa  = (const float*)d_in[4];  // (256,)
    const float* ba  = (const float*)d_in[5];  // ()

    float* out = (float*)d_out;
    const int out_elems = Bv * Sv * Hv;        // 524288
    const int aw_elems  = Bv * Sv * Sv;        // 1048576
    float* aw_out = (out_size >= out_elems + aw_elems) ? out + out_elems : nullptr;

    // k1: projections  g_P[2048][512]
    {
        dim3 grid((2 * Hv) / 64, (Bv * Sv) / 32);   // 8 x 64 = 512 blocks
        k1_proj<<<grid, 256>>>(h, Wt, Wtp, bh);
    }
    // k2: pairwise tanh scores + sigmoid
    {
        dim3 grid(Sv / TT, Sv / TT, Bv);            // 16 x 16 x 4
        k2_scores<<<grid, 256>>>(Wa, ba);
    }
    // k3: softmax rows
    {
        k3_softmax<<<(Bv * Sv) / 8, 256>>>(aw_out);
    }
    // k4: output = AW @ h
    {
        dim3 grid(Hv / 64, Sv / 32, Bv);            // 4 x 16 x 4 = 256 blocks
        k4_out<<<grid, 256>>>(h, out);
    }
}

// round 14
// speedup vs baseline: 1.0063x; 1.0021x over previous
#include <cuda_runtime.h>
#include <cuda_bf16.h>
#include <cstdint>

// Shapes (fixed by problem)
#define Bv 4
#define Sv 512
#define Hv 256

// Scratch (device globals: no allocation allowed in kernel_launch)
__device__ float g_P[(Bv * Sv) * (2 * Hv)];   // [m][0:256]=h@W_t, [256:512]=h@W_t' + b_h
__device__ float g_S[Bv * Sv * Sv];           // sigmoid(scores)
__device__ float g_AW[Bv * Sv * Sv];          // softmax(attention weights)

__device__ __forceinline__ float fast_tanh(float x) {
    float y;
    asm("tanh.approx.f32 %0, %1;" : "=f"(y) : "f"(x));
    return y;
}

// ---------------------------------------------------------------------------
// Kernel 1: fused projection GEMM
//   g_P[M=2048][N=512] = h[2048][256] @ [W_t | W_t'] ; cols >=256 get +b_h
// TILE 32(m) x 64(n), BK=32, 256 threads, 2x4 microtile, float4 gmem I/O,
// A transposed in smem (k-major) -> inner loop: LDS.64 + LDS.128 + 8 FFMA.
// Grid 8 x 64 = 512 blocks.
// ---------------------------------------------------------------------------
__global__ __launch_bounds__(256) void k1_proj(
    const float* __restrict__ h,
    const float* __restrict__ Wt,
    const float* __restrict__ Wtp,
    const float* __restrict__ bh)
{
    __shared__ alignas(16) float sA[32][34];   // [k][m]
    __shared__ alignas(16) float sB[32][68];   // [k][n]

    const int tid = threadIdx.x;
    const int bm  = blockIdx.y * 32;
    const int bn  = blockIdx.x * 64;
    const int tx  = tid & 15;        // n: 16 * 4
    const int ty  = tid >> 4;        // m: 16 * 2

    const bool second = (bn >= Hv);
    const float* __restrict__ W = second ? Wtp : Wt;
    const int wcol = bn & (Hv - 1);

    // A-load mapping: one float4 per thread per k-step
    const int ar  = tid >> 3;         // 0..31 (m row)
    const int ac4 = (tid & 7) * 4;    // 0..28 (k col)

    float acc[2][4] = {};

    for (int k0 = 0; k0 < Hv; k0 += 32) {
        float4 av = *(const float4*)&h[(bm + ar) * Hv + k0 + ac4];
        sA[ac4 + 0][ar] = av.x;
        sA[ac4 + 1][ar] = av.y;
        sA[ac4 + 2][ar] = av.z;
        sA[ac4 + 3][ar] = av.w;
        #pragma unroll
        for (int j = 0; j < 2; j++) {
            int idx = tid + j * 256;
            int rb  = idx >> 4;            // 0..31 (k)
            int cb4 = (idx & 15) * 4;      // 0..60 (n)
            *(float4*)&sB[rb][cb4] =
                *(const float4*)&W[(k0 + rb) * Hv + wcol + cb4];
        }
        __syncthreads();

        #pragma unroll
        for (int k = 0; k < 32; k++) {
            float2 a = *(const float2*)&sA[k][ty * 2];
            float4 b = *(const float4*)&sB[k][tx * 4];
            acc[0][0] = fmaf(a.x, b.x, acc[0][0]);
            acc[0][1] = fmaf(a.x, b.y, acc[0][1]);
            acc[0][2] = fmaf(a.x, b.z, acc[0][2]);
            acc[0][3] = fmaf(a.x, b.w, acc[0][3]);
            acc[1][0] = fmaf(a.y, b.x, acc[1][0]);
            acc[1][1] = fmaf(a.y, b.y, acc[1][1]);
            acc[1][2] = fmaf(a.y, b.z, acc[1][2]);
            acc[1][3] = fmaf(a.y, b.w, acc[1][3]);
        }
        __syncthreads();
    }

    float4 bias = make_float4(0.f, 0.f, 0.f, 0.f);
    if (second) bias = *(const float4*)&bh[wcol + tx * 4];

    #pragma unroll
    for (int i = 0; i < 2; i++) {
        int m = bm + ty * 2 + i;
        float4 v = make_float4(acc[i][0] + bias.x, acc[i][1] + bias.y,
                               acc[i][2] + bias.z, acc[i][3] + bias.w);
        *(float4*)&g_P[m * (2 * Hv) + bn + tx * 4] = v;
    }
}

// ---------------------------------------------------------------------------
// Kernel 2: pairwise scores (MUFU-bound, near the tanh floor)
//   S[b,t,t'] = sigmoid( b_a + sum_h W_a[h] * tanh(ht[b,t,h] + htp[b,t',h]) )
// ---------------------------------------------------------------------------
#define TT 32
#define HC 64
__global__ __launch_bounds__(256) void k2_scores(
    const float* __restrict__ Wa,
    const float* __restrict__ ba)
{
    __shared__ float sA[TT][HC + 1];
    __shared__ float sB[TT][HC + 1];
    __shared__ float sW[HC];

    const int b   = blockIdx.z;
    const int t0  = blockIdx.y * TT;
    const int tp0 = blockIdx.x * TT;
    const int tid = threadIdx.x;
    const int tx = tid & 15, ty = tid >> 4;

    const float* Pb = g_P + (size_t)b * Sv * (2 * Hv);

    float acc00 = 0.f, acc01 = 0.f, acc10 = 0.f, acc11 = 0.f;

    for (int h0 = 0; h0 < Hv; h0 += HC) {
        #pragma unroll
        for (int i = 0; i < 8; i++) {
            int idx = tid + i * 256;
            int r = idx >> 6, c = idx & 63;
            sA[r][c] = Pb[(t0  + r) * (2 * Hv) + h0 + c];          // ht rows
            sB[r][c] = Pb[(tp0 + r) * (2 * Hv) + Hv + h0 + c];     // htp+b_h rows
        }
        if (tid < HC) sW[tid] = Wa[h0 + tid];
        __syncthreads();

        #pragma unroll
        for (int hh = 0; hh < HC; hh++) {
            float w  = sW[hh];
            float a0 = sA[2 * ty][hh];
            float a1 = sA[2 * ty + 1][hh];
            float b0 = sB[2 * tx][hh];
            float b1 = sB[2 * tx + 1][hh];
            acc00 = fmaf(w, fast_tanh(a0 + b0), acc00);
            acc01 = fmaf(w, fast_tanh(a0 + b1), acc01);
            acc10 = fmaf(w, fast_tanh(a1 + b0), acc10);
            acc11 = fmaf(w, fast_tanh(a1 + b1), acc11);
        }
        __syncthreads();
    }

    const float bav = ba[0];
    float* Sb = g_S + (size_t)b * Sv * Sv;
    float r[2][2] = {{acc00, acc01}, {acc10, acc11}};
    #pragma unroll
    for (int i = 0; i < 2; i++) {
        #pragma unroll
        for (int j = 0; j < 2; j++) {
            float x = r[i][j] + bav;
            float sg = 1.0f / (1.0f + __expf(-x));
            Sb[(t0 + 2 * ty + i) * Sv + (tp0 + 2 * tx + j)] = sg;
        }
    }
}

// ---------------------------------------------------------------------------
// Kernel 3: row softmax. One warp per row of 512 (float4 vectorized).
// ---------------------------------------------------------------------------
__global__ __launch_bounds__(256) void k3_softmax(float* __restrict__ aw_out)
{
    const int row  = blockIdx.x * 8 + (threadIdx.x >> 5);
    const int lane = threadIdx.x & 31;
    const float4* src = (const float4*)(g_S + (size_t)row * Sv);

    float4 v[4];
    float mx = -1e30f;
    #pragma unroll
    for (int i = 0; i < 4; i++) {
        v[i] = src[i * 32 + lane];
        mx = fmaxf(mx, fmaxf(fmaxf(v[i].x, v[i].y), fmaxf(v[i].z, v[i].w)));
    }
    #pragma unroll
    for (int o = 16; o > 0; o >>= 1)
        mx = fmaxf(mx, __shfl_xor_sync(0xffffffffu, mx, o));

    float sum = 0.f;
    #pragma unroll
    for (int i = 0; i < 4; i++) {
        v[i].x = __expf(v[i].x - mx);
        v[i].y = __expf(v[i].y - mx);
        v[i].z = __expf(v[i].z - mx);
        v[i].w = __expf(v[i].w - mx);
        sum += v[i].x + v[i].y + v[i].z + v[i].w;
    }
    #pragma unroll
    for (int o = 16; o > 0; o >>= 1)
        sum += __shfl_xor_sync(0xffffffffu, sum, o);

    const float inv = 1.0f / sum;
    float4* dst = (float4*)(g_AW + (size_t)row * Sv);
    #pragma unroll
    for (int i = 0; i < 4; i++) {
        float4 o4 = v[i];
        o4.x *= inv; o4.y *= inv; o4.z *= inv; o4.w *= inv;
        dst[i * 32 + lane] = o4;
    }
    if (aw_out) {
        float4* dst2 = (float4*)(aw_out + (size_t)row * Sv);
        #pragma unroll
        for (int i = 0; i < 4; i++) {
            float4 o4 = v[i];
            o4.x *= inv; o4.y *= inv; o4.z *= inv; o4.w *= inv;
            dst2[i * 32 + lane] = o4;
        }
    }
}

// ---------------------------------------------------------------------------
// Kernel 4: output[b] = AW[b](512x512) @ h[b](512x256)
// Same tiling as k1: 32x64 tile, BK=32, 256 threads, 2x4 microtile.
// Grid (256/64=4, 512/32=16, 4) = 256 blocks.
// ---------------------------------------------------------------------------
__global__ __launch_bounds__(256) void k4_out(
    const float* __restrict__ h,
    float* __restrict__ out)
{
    __shared__ alignas(16) float sA[32][34];   // [k][m]
    __shared__ alignas(16) float sB[32][68];   // [k][n]

    const int b   = blockIdx.z;
    const int bm  = blockIdx.y * 32;   // t rows
    const int bn  = blockIdx.x * 64;   // h cols
    const int tid = threadIdx.x;
    const int tx  = tid & 15;
    const int ty  = tid >> 4;

    const float* __restrict__ A  = g_AW + (size_t)b * Sv * Sv;   // 512x512
    const float* __restrict__ Bm = h + (size_t)b * Sv * Hv;      // 512x256
    float* C = out + (size_t)b * Sv * Hv;

    const int ar  = tid >> 3;
    const int ac4 = (tid & 7) * 4;

    float acc[2][4] = {};

    for (int k0 = 0; k0 < Sv; k0 += 32) {
        float4 av = *(const float4*)&A[(bm + ar) * Sv + k0 + ac4];
        sA[ac4 + 0][ar] = av.x;
        sA[ac4 + 1][ar] = av.y;
        sA[ac4 + 2][ar] = av.z;
        sA[ac4 + 3][ar] = av.w;
        #pragma unroll
        for (int j = 0; j < 2; j++) {
            int idx = tid + j * 256;
            int rb  = idx >> 4;
            int cb4 = (idx & 15) * 4;
            *(float4*)&sB[rb][cb4] =
                *(const float4*)&Bm[(k0 + rb) * Hv + bn + cb4];
        }
        __syncthreads();

        #pragma unroll
        for (int k = 0; k < 32; k++) {
            float2 a = *(const float2*)&sA[k][ty * 2];
            float4 bb = *(const float4*)&sB[k][tx * 4];
            acc[0][0] = fmaf(a.x, bb.x, acc[0][0]);
            acc[0][1] = fmaf(a.x, bb.y, acc[0][1]);
            acc[0][2] = fmaf(a.x, bb.z, acc[0][2]);
            acc[0][3] = fmaf(a.x, bb.w, acc[0][3]);
            acc[1][0] = fmaf(a.y, bb.x, acc[1][0]);
            acc[1][1] = fmaf(a.y, bb.y, acc[1][1]);
            acc[1][2] = fmaf(a.y, bb.z, acc[1][2]);
            acc[1][3] = fmaf(a.y, bb.w, acc[1][3]);
        }
        __syncthreads();
    }

    #pragma unroll
    for (int i = 0; i < 2; i++) {
        int m = bm + ty * 2 + i;
        float4 v = make_float4(acc[i][0], acc[i][1], acc[i][2], acc[i][3]);
        *(float4*)&C[m * Hv + bn + tx * 4] = v;
    }
}

// ---------------------------------------------------------------------------
extern "C" void kernel_launch(void* const* d_in, const int* in_sizes, int n_in,
                              void* d_out, int out_size)
{
    const float* h   = (const float*)d_in[0];  // (4,512,256)
    const float* Wt  = (const float*)d_in[1];  // (256,256)
    const float* Wtp = (const float*)d_in[2];  // (256,256)
    const float* bh  = (const float*)d_in[3];  // (256,)
    const float* Wa  = (const float*)d_in[4];  // (256,)
    const float* ba  = (const float*)d_in[5];  // ()

    float* out = (float*)d_out;
    const int out_elems = Bv * Sv * Hv;        // 524288
    const int aw_elems  = Bv * Sv * Sv;        // 1048576
    float* aw_out = (out_size >= out_elems + aw_elems) ? out + out_elems : nullptr;

    // k1: projections  g_P[2048][512]
    {
        dim3 grid((2 * Hv) / 64, (Bv * Sv) / 32);   // 8 x 64 = 512 blocks
        k1_proj<<<grid, 256>>>(h, Wt, Wtp, bh);
    }
    // k2: pairwise tanh scores + sigmoid
    {
        dim3 grid(Sv / TT, Sv / TT, Bv);            // 16 x 16 x 4
        k2_scores<<<grid, 256>>>(Wa, ba);
    }
    // k3: softmax rows
    {
        k3_softmax<<<(Bv * Sv) / 8, 256>>>(aw_out);
    }
    // k4: output = AW @ h
    {
        dim3 grid(Hv / 64, Sv / 32, Bv);            // 4 x 16 x 4 = 256 blocks
        k4_out<<<grid, 256>>>(h, out);
    }
}